// round 6
// baseline (speedup 1.0000x reference)
#include <cuda_runtime.h>

// out[i, :] = sum_k ppr_scores[i,k] * x[ppr_idx[i,k], :]
// N=100000, K=32, D=128 (fp32). One warp per output row; lane l holds
// (idx[l], score[l]) broadcast via shfl.
//
// R6: replace the 512B LDG.128 row read (4 lines = 4 within-LDG replay
// wavefronts @ ~2.07 cyc/wf) with 4x LDG.32, each coalesced to exactly one
// 128B line (1 wavefront @ ~1.0 cyc/wf cross-LDG rate). Same wavefront
// count, ~half the L1tex cost; new bound is the LSU issue floor
// (~1.82 cyc/LDG/SM ~= 71us). Lane l owns features {l, l+32, l+64, l+96};
// output written as 4 coalesced single-line STG.32. Batch of 2 rows keeps
// 8 loads in flight within the proven 32-reg / occ~89% envelope.

#define KNEIGH 32
#define DFEAT  128

__global__ __launch_bounds__(256) void ppr_gather_kernel(
    const float* __restrict__ x,      // [N, 128]
    const int*   __restrict__ idx,    // [N, 32]
    const float* __restrict__ sc,     // [N, 32]
    float*       __restrict__ out,    // [N, 128]
    int n)
{
    const int warp = (blockIdx.x * blockDim.x + threadIdx.x) >> 5;
    const int lane = threadIdx.x & 31;
    if (warp >= n) return;

    // Lane-held neighbor index/score for this row (K == warpSize).
    const int   my_j = idx[warp * KNEIGH + lane];
    const float my_s = sc[warp * KNEIGH + lane];

    float acc0 = 0.f, acc1 = 0.f, acc2 = 0.f, acc3 = 0.f;

    #pragma unroll
    for (int k = 0; k < KNEIGH; k += 2) {
        const int   j0 = __shfl_sync(0xffffffffu, my_j, k);
        const float s0 = __shfl_sync(0xffffffffu, my_s, k);
        const int   j1 = __shfl_sync(0xffffffffu, my_j, k + 1);
        const float s1 = __shfl_sync(0xffffffffu, my_s, k + 1);

        const float* r0 = x + (long long)j0 * DFEAT + lane;
        const float* r1 = x + (long long)j1 * DFEAT + lane;

        // 8 independent single-line (128B) coalesced loads in flight.
        const float a0 = r0[0];
        const float a1 = r0[32];
        const float a2 = r0[64];
        const float a3 = r0[96];
        const float b0 = r1[0];
        const float b1 = r1[32];
        const float b2 = r1[64];
        const float b3 = r1[96];

        acc0 += s0 * a0 + s1 * b0;
        acc1 += s0 * a1 + s1 * b1;
        acc2 += s0 * a2 + s1 * b2;
        acc3 += s0 * a3 + s1 * b3;
    }

    float* o = out + (long long)warp * DFEAT + lane;
    o[0]  = acc0;
    o[32] = acc1;
    o[64] = acc2;
    o[96] = acc3;
}

extern "C" void kernel_launch(void* const* d_in, const int* in_sizes, int n_in,
                              void* d_out, int out_size)
{
    const float* x   = (const float*)d_in[0];   // [N, D] fp32
    const int*   idx = (const int*)d_in[1];     // [N, K] int32
    const float* sc  = (const float*)d_in[2];   // [N, K] fp32
    float*       out = (float*)d_out;           // [N, D] fp32

    const int n = in_sizes[1] / KNEIGH;         // N rows

    const int warps_per_block = 8;              // 256 threads
    const int blocks = (n + warps_per_block - 1) / warps_per_block;
    ppr_gather_kernel<<<blocks, warps_per_block * 32>>>(x, idx, sc, out, n);
}

// round 7
// speedup vs baseline: 1.1290x; 1.1290x over previous
#include <cuda_runtime.h>

// out[i, :] = sum_k ppr_scores[i,k] * x[ppr_idx[i,k], :]
// N=100000, K=32, D=128 (fp32). One warp per output row; lane l holds
// (idx[l], score[l]) broadcast via shfl; warp reads each neighbor row as one
// coalesced 512B LDG.128 (4 sectors). x (51MB) is L2-resident.
//
// R7 = R1 (proven best, 80.4us) with 512-thread CTAs (same occupancy,
// half the CTA boundaries). Roofline argument for why ~80us is the floor:
// 12.8M compulsory 128B L1tex wavefronts x ~2.07 cyc/wf / 148 SMs ~= 80us.
// DRAM traffic is exactly compulsory (127MB), L2 hit rate maximal, and all
// alternate data paths (TMA, LDGSTS+smem, scatter+atomics, LDG.32 split)
// were measured or bounded strictly worse in R2-R6.

#define KNEIGH 32
#define DVEC   32   // D/4 float4 per row

__global__ __launch_bounds__(512) void ppr_gather_kernel(
    const float4* __restrict__ x,      // [N, 32] float4
    const int*    __restrict__ idx,    // [N, 32]
    const float*  __restrict__ sc,     // [N, 32]
    float4*       __restrict__ out,    // [N, 32] float4
    int n)
{
    const int warp = (blockIdx.x * blockDim.x + threadIdx.x) >> 5;
    const int lane = threadIdx.x & 31;
    if (warp >= n) return;

    // Lane-held neighbor index/score for this row (K == warpSize).
    const int   my_j = idx[warp * KNEIGH + lane];
    const float my_s = sc[warp * KNEIGH + lane];

    float4 acc = make_float4(0.f, 0.f, 0.f, 0.f);

    #pragma unroll
    for (int k = 0; k < KNEIGH; k += 8) {
        // 8 independent 512B row loads in flight per warp.
        float4 v[8];
        float  s[8];
        #pragma unroll
        for (int u = 0; u < 8; ++u) {
            const int jk = __shfl_sync(0xffffffffu, my_j, k + u);
            s[u]         = __shfl_sync(0xffffffffu, my_s, k + u);
            v[u]         = x[(long long)jk * DVEC + lane];
        }
        #pragma unroll
        for (int u = 0; u < 8; ++u) {
            acc.x += s[u] * v[u].x;
            acc.y += s[u] * v[u].y;
            acc.z += s[u] * v[u].z;
            acc.w += s[u] * v[u].w;
        }
    }

    out[warp * DVEC + lane] = acc;
}

extern "C" void kernel_launch(void* const* d_in, const int* in_sizes, int n_in,
                              void* d_out, int out_size)
{
    const float4* x   = (const float4*)d_in[0];   // [N, D] fp32
    const int*    idx = (const int*)d_in[1];      // [N, K] int32
    const float*  sc  = (const float*)d_in[2];    // [N, K] fp32
    float4*       out = (float4*)d_out;           // [N, D] fp32

    const int n = in_sizes[1] / KNEIGH;           // N rows

    const int warps_per_block = 16;               // 512 threads
    const int blocks = (n + warps_per_block - 1) / warps_per_block;
    ppr_gather_kernel<<<blocks, warps_per_block * 32>>>(x, idx, sc, out, n);
}

// round 8
// speedup vs baseline: 1.3778x; 1.2203x over previous
#include <cuda_runtime.h>
#include <cuda_fp16.h>

// out[i, :] = sum_k ppr_scores[i,k] * x[ppr_idx[i,k], :]
// N=100000, K=32, D=128 (fp32 in/out). rel_err budget is 1e-3; fp32 path sits
// at 1.3e-7 and is pinned at the L1tex/LTS wavefront floor (~80us for 12.8M
// compulsory 128B wavefronts). R8 halves gather bytes: per-launch convert
// x -> fp16 into __device__ scratch (51MB read + 25.6MB write, ~12us), then
// gather 256B fp16 rows (2 wavefronts/row instead of 4). fp32 accumulate.
// Expected rel_err ~1e-4 (fp16 storage rounding only), well inside budget.

#define KNEIGH 32
#define DFEAT  128
#define NMAX   100000

// fp16 copy of x: 100000 * 128 * 2B = 25.6 MB (L2-resident).
__device__ __align__(16) static __half g_xh[(size_t)NMAX * DFEAT];

// ---------------- pass 1: fp32 -> fp16 convert ----------------
// Each thread converts 8 floats (two float4) into one 16B uint4 store.
__global__ __launch_bounds__(256) void cvt_kernel(
    const float4* __restrict__ x, int n8)
{
    const int i = blockIdx.x * blockDim.x + threadIdx.x;
    if (i >= n8) return;

    const float4 a = x[2 * i];
    const float4 b = x[2 * i + 1];

    __half2 h0 = __floats2half2_rn(a.x, a.y);
    __half2 h1 = __floats2half2_rn(a.z, a.w);
    __half2 h2 = __floats2half2_rn(b.x, b.y);
    __half2 h3 = __floats2half2_rn(b.z, b.w);

    uint4 p;
    p.x = *reinterpret_cast<unsigned*>(&h0);
    p.y = *reinterpret_cast<unsigned*>(&h1);
    p.z = *reinterpret_cast<unsigned*>(&h2);
    p.w = *reinterpret_cast<unsigned*>(&h3);
    reinterpret_cast<uint4*>(g_xh)[i] = p;
}

// ---------------- pass 2: gather-reduce from fp16 rows ----------------
// One warp per output row; lane l holds (idx[l], score[l]) broadcast via
// shfl. Each neighbor row is 256B: lane l loads one uint2 (features
// 4l..4l+3), so the warp read is exactly 2 coalesced 128B lines.
__global__ __launch_bounds__(256) void ppr_gather_kernel(
    const int*   __restrict__ idx,    // [N, 32]
    const float* __restrict__ sc,     // [N, 32]
    float4*      __restrict__ out,    // [N, 32] float4
    int n)
{
    const int warp = (blockIdx.x * blockDim.x + threadIdx.x) >> 5;
    const int lane = threadIdx.x & 31;
    if (warp >= n) return;

    const int   my_j = idx[warp * KNEIGH + lane];
    const float my_s = sc[warp * KNEIGH + lane];

    float acc0 = 0.f, acc1 = 0.f, acc2 = 0.f, acc3 = 0.f;

    #pragma unroll
    for (int k = 0; k < KNEIGH; k += 8) {
        // 8 independent 256B row loads in flight per warp.
        uint2 v[8];
        float s[8];
        #pragma unroll
        for (int u = 0; u < 8; ++u) {
            const int jk = __shfl_sync(0xffffffffu, my_j, k + u);
            s[u]         = __shfl_sync(0xffffffffu, my_s, k + u);
            v[u] = reinterpret_cast<const uint2*>(
                       g_xh + (size_t)jk * DFEAT)[lane];
        }
        #pragma unroll
        for (int u = 0; u < 8; ++u) {
            const __half2 h0 = *reinterpret_cast<const __half2*>(&v[u].x);
            const __half2 h1 = *reinterpret_cast<const __half2*>(&v[u].y);
            const float2 f0 = __half22float2(h0);
            const float2 f1 = __half22float2(h1);
            acc0 += s[u] * f0.x;
            acc1 += s[u] * f0.y;
            acc2 += s[u] * f1.x;
            acc3 += s[u] * f1.y;
        }
    }

    // Lane l owns features 4l..4l+3 == float4 element l of the out row.
    out[warp * (DFEAT / 4) + lane] = make_float4(acc0, acc1, acc2, acc3);
}

extern "C" void kernel_launch(void* const* d_in, const int* in_sizes, int n_in,
                              void* d_out, int out_size)
{
    const float4* x   = (const float4*)d_in[0];   // [N, D] fp32
    const int*    idx = (const int*)d_in[1];      // [N, K] int32
    const float*  sc  = (const float*)d_in[2];    // [N, K] fp32
    float4*       out = (float4*)d_out;           // [N, D] fp32

    const int n  = in_sizes[1] / KNEIGH;          // N rows
    const int n8 = in_sizes[0] / 8;               // convert units (8 floats)

    cvt_kernel<<<(n8 + 255) / 256, 256>>>(x, n8);

    const int warps_per_block = 8;                // 256 threads
    const int blocks = (n + warps_per_block - 1) / warps_per_block;
    ppr_gather_kernel<<<blocks, warps_per_block * 32>>>(idx, sc, out, n);
}

// round 9
// speedup vs baseline: 1.4680x; 1.0655x over previous
#include <cuda_runtime.h>
#include <cuda_fp16.h>

// out[i, :] = sum_k ppr_scores[i,k] * x[ppr_idx[i,k], :]
// N=100000, K=32, D=128 (fp32 in/out, 1e-3 rel-err budget).
// Two-pass: (1) convert x -> fp16 scratch (~12us, HBM-bound floor);
// (2) gather 256B fp16 rows, fp32 accumulate.
//
// R9 gather: half-warp row pairing. One LDG.128 fetches TWO neighbor rows
// (lanes 0-15 -> row j[2u], lanes 16-31 -> row j[2u+1]; uint4 = 8 features
// per lane). Same wavefronts/byte, but LDG and SHFL issue counts halve
// (R8 showed issue=65% riding on top of the L1tex plateau). Epilogue folds
// even/odd-k partials with 8 shfl_xor(16) and stores one coalesced
// STG.128 per row.

#define KNEIGH 32
#define DFEAT  128
#define NMAX   100000

// fp16 copy of x: 100000 * 128 * 2B = 25.6 MB (L2-resident).
__device__ __align__(16) static __half g_xh[(size_t)NMAX * DFEAT];

// ---------------- pass 1: fp32 -> fp16 convert ----------------
__global__ __launch_bounds__(256) void cvt_kernel(
    const float4* __restrict__ x, int n8)
{
    const int i = blockIdx.x * blockDim.x + threadIdx.x;
    if (i >= n8) return;

    const float4 a = x[2 * i];
    const float4 b = x[2 * i + 1];

    __half2 h0 = __floats2half2_rn(a.x, a.y);
    __half2 h1 = __floats2half2_rn(a.z, a.w);
    __half2 h2 = __floats2half2_rn(b.x, b.y);
    __half2 h3 = __floats2half2_rn(b.z, b.w);

    uint4 p;
    p.x = *reinterpret_cast<unsigned*>(&h0);
    p.y = *reinterpret_cast<unsigned*>(&h1);
    p.z = *reinterpret_cast<unsigned*>(&h2);
    p.w = *reinterpret_cast<unsigned*>(&h3);
    reinterpret_cast<uint4*>(g_xh)[i] = p;
}

// ---------------- pass 2: gather-reduce ----------------
__global__ __launch_bounds__(256) void ppr_gather_kernel(
    const int*   __restrict__ idx,    // [N, 32]
    const float* __restrict__ sc,     // [N, 32]
    float4*      __restrict__ out,    // [N, 32] float4
    int n)
{
    const int warp = (blockIdx.x * blockDim.x + threadIdx.x) >> 5;
    const int lane = threadIdx.x & 31;
    if (warp >= n) return;

    const int half_id = lane >> 4;        // 0: even-k rows, 1: odd-k rows
    const int fbase16 = lane & 15;        // 16B-chunk index within a row

    // Lane-held neighbor index/score for k == lane.
    const int   my_j = idx[warp * KNEIGH + lane];
    const float my_s = sc[warp * KNEIGH + lane];

    float a0 = 0.f, a1 = 0.f, a2 = 0.f, a3 = 0.f;
    float a4 = 0.f, a5 = 0.f, a6 = 0.f, a7 = 0.f;

    #pragma unroll
    for (int i = 0; i < KNEIGH / 2; i += 2) {
        // Two LDG.128 in flight, each covering 2 neighbor rows (4 rows/iter).
        const int   jA = __shfl_sync(0xffffffffu, my_j, 2 * i + half_id);
        const float sA = __shfl_sync(0xffffffffu, my_s, 2 * i + half_id);
        const int   jB = __shfl_sync(0xffffffffu, my_j, 2 * i + 2 + half_id);
        const float sB = __shfl_sync(0xffffffffu, my_s, 2 * i + 2 + half_id);

        const uint4 vA = reinterpret_cast<const uint4*>(
                             g_xh + (size_t)jA * DFEAT)[fbase16];
        const uint4 vB = reinterpret_cast<const uint4*>(
                             g_xh + (size_t)jB * DFEAT)[fbase16];

        {
            const float2 f0 = __half22float2(*reinterpret_cast<const __half2*>(&vA.x));
            const float2 f1 = __half22float2(*reinterpret_cast<const __half2*>(&vA.y));
            const float2 f2 = __half22float2(*reinterpret_cast<const __half2*>(&vA.z));
            const float2 f3 = __half22float2(*reinterpret_cast<const __half2*>(&vA.w));
            a0 += sA * f0.x;  a1 += sA * f0.y;
            a2 += sA * f1.x;  a3 += sA * f1.y;
            a4 += sA * f2.x;  a5 += sA * f2.y;
            a6 += sA * f3.x;  a7 += sA * f3.y;
        }
        {
            const float2 f0 = __half22float2(*reinterpret_cast<const __half2*>(&vB.x));
            const float2 f1 = __half22float2(*reinterpret_cast<const __half2*>(&vB.y));
            const float2 f2 = __half22float2(*reinterpret_cast<const __half2*>(&vB.z));
            const float2 f3 = __half22float2(*reinterpret_cast<const __half2*>(&vB.w));
            a0 += sB * f0.x;  a1 += sB * f0.y;
            a2 += sB * f1.x;  a3 += sB * f1.y;
            a4 += sB * f2.x;  a5 += sB * f2.y;
            a6 += sB * f3.x;  a7 += sB * f3.y;
        }
    }

    // Fold even-k (lanes 0-15) and odd-k (lanes 16-31) partial sums.
    a0 += __shfl_xor_sync(0xffffffffu, a0, 16);
    a1 += __shfl_xor_sync(0xffffffffu, a1, 16);
    a2 += __shfl_xor_sync(0xffffffffu, a2, 16);
    a3 += __shfl_xor_sync(0xffffffffu, a3, 16);
    a4 += __shfl_xor_sync(0xffffffffu, a4, 16);
    a5 += __shfl_xor_sync(0xffffffffu, a5, 16);
    a6 += __shfl_xor_sync(0xffffffffu, a6, 16);
    a7 += __shfl_xor_sync(0xffffffffu, a7, 16);

    // Lane owns features fbase16*8 .. +7; low half stores the first float4,
    // high half the second. Union = one contiguous 512B STG per row.
    const float4 r = half_id ? make_float4(a4, a5, a6, a7)
                             : make_float4(a0, a1, a2, a3);
    out[warp * (DFEAT / 4) + fbase16 * 2 + half_id] = r;
}

extern "C" void kernel_launch(void* const* d_in, const int* in_sizes, int n_in,
                              void* d_out, int out_size)
{
    const float4* x   = (const float4*)d_in[0];   // [N, D] fp32
    const int*    idx = (const int*)d_in[1];      // [N, K] int32
    const float*  sc  = (const float*)d_in[2];    // [N, K] fp32
    float4*       out = (float4*)d_out;           // [N, D] fp32

    const int n  = in_sizes[1] / KNEIGH;          // N rows
    const int n8 = in_sizes[0] / 8;               // convert units (8 floats)

    cvt_kernel<<<(n8 + 255) / 256, 256>>>(x, n8);

    const int warps_per_block = 8;                // 256 threads
    const int blocks = (n + warps_per_block - 1) / warps_per_block;
    ppr_gather_kernel<<<blocks, warps_per_block * 32>>>(idx, sc, out, n);
}